// round 13
// baseline (speedup 1.0000x reference)
#include <cuda_runtime.h>
#include <cuda_bf16.h>

// ---------------------------------------------------------------------------
// Cl(4,1) CGA sandwich:  out = decode( (M P) ~M ),  M even versor, P grade-1.
// SCATTER-FORM second contraction: each odd component mx_io is computed and
// immediately accumulated into the 5 grade-1 outputs q[0..4], so the mx[16]
// array is never materialized. Live set drops from ~37+ to ~28 registers;
// __launch_bounds__(256, 8) caps regs at 32 -> 8 CTAs/SM = 100% theoretical
// occupancy (vs 75% at 40 regs). More resident warps -> more in-flight loads
// -> higher sustained DRAM (the measured occ<->DRAM correlation).
// I/O structure identical to the proven-best baseline (1 pt/thread,
// 4x LDG.128 versor, scalar x/out, default cache policy).
// ---------------------------------------------------------------------------

namespace cga {

__host__ __device__ constexpr int popc5(int x) {
    int c = 0;
    for (int i = 0; i < 5; i++) c += (x >> i) & 1;
    return c;
}

__host__ __device__ constexpr int even_blade(int i) {
    constexpr int E[16] = {0,3,5,6,9,10,12,15,17,18,20,23,24,27,29,30};
    return E[i];
}
__host__ __device__ constexpr int odd_blade(int i) {
    constexpr int O[16] = {1,2,4,7,8,11,13,14,16,19,21,22,25,26,28,31};
    return O[i];
}
__host__ __device__ constexpr int g1_blade(int i) {
    constexpr int G[5] = {1,2,4,8,16};
    return G[i];
}
__host__ __device__ constexpr int even_index_of(int b) {
    for (int i = 0; i < 16; i++) if (even_blade(i) == b) return i;
    return -1;
}

// sign of blade product a*b: reorder sign + metric (only e5 = bit 4 squares -1)
__host__ __device__ constexpr float blade_sign(int a, int b) {
    int s = 0;
    for (int t = a >> 1; t; t >>= 1) s += popc5(t & b);
    float sign = (s & 1) ? -1.0f : 1.0f;
    if ((a & b) & 16) sign = -sign;
    return sign;
}

__host__ __device__ constexpr float rev_sign(int b) {
    int g = popc5(b);
    return ((g * (g - 1) / 2) & 1) ? -1.0f : 1.0f;
}

// ---- first contraction (gather): mx_io = sum_ip mx_sgn(io,ip)*v[mx_ie]*p[ip]
__host__ __device__ constexpr int   mx_ie (int io, int ip) { return even_index_of(odd_blade(io) ^ g1_blade(ip)); }
__host__ __device__ constexpr float mx_sgn(int io, int ip) { return blade_sign(odd_blade(io) ^ g1_blade(ip), g1_blade(ip)); }

// ---- second contraction (scatter): q[iq] += sc_sgn(io,iq)*mx_io*v[sc_ie(io,iq)]
// for odd blade a = odd_blade(io) and output c = g1_blade(iq), the even blade
// is b = a ^ c; term sign = blade_sign(a, b) * rev_sign(b).
__host__ __device__ constexpr int   sc_ie (int io, int iq) { return even_index_of(odd_blade(io) ^ g1_blade(iq)); }
__host__ __device__ constexpr float sc_sgn(int io, int iq) {
    return blade_sign(odd_blade(io), odd_blade(io) ^ g1_blade(iq))
         * rev_sign(odd_blade(io) ^ g1_blade(iq));
}

// ---- template-recursive unrollers (compile-time indices guaranteed) ----

// mx_io = sum_{ip<=IP} terms
template<int IO, int IP>
struct MxTerm {
    static __device__ __forceinline__ float run(const float (&v)[16], const float (&p)[5]) {
        float prev = MxTerm<IO, IP - 1>::run(v, p);
        constexpr int   ie = mx_ie(IO, IP);
        constexpr float s  = mx_sgn(IO, IP);
        return (s > 0.0f) ? fmaf(v[ie], p[IP], prev) : fmaf(-v[ie], p[IP], prev);
    }
};
template<int IO>
struct MxTerm<IO, -1> {
    static __device__ __forceinline__ float run(const float (&)[16], const float (&)[5]) { return 0.0f; }
};

// scatter mx_io into q[0..IQ]
template<int IO, int IQ>
struct Scatter {
    static __device__ __forceinline__ void run(float (&q)[5], float mxv, const float (&v)[16]) {
        Scatter<IO, IQ - 1>::run(q, mxv, v);
        constexpr int   ie = sc_ie(IO, IQ);
        constexpr float s  = sc_sgn(IO, IQ);
        q[IQ] = (s > 0.0f) ? fmaf(mxv, v[ie], q[IQ]) : fmaf(-mxv, v[ie], q[IQ]);
    }
};
template<int IO>
struct Scatter<IO, -1> {
    static __device__ __forceinline__ void run(float (&)[5], float, const float (&)[16]) {}
};

// for each odd component: compute then immediately scatter (mx never stored)
template<int IO>
struct FusedAll {
    static __device__ __forceinline__ void run(float (&q)[5], const float (&v)[16], const float (&p)[5]) {
        FusedAll<IO - 1>::run(q, v, p);
        float mxv = MxTerm<IO, 4>::run(v, p);
        Scatter<IO, 4>::run(q, mxv, v);
    }
};
template<>
struct FusedAll<-1> {
    static __device__ __forceinline__ void run(float (&)[5], const float (&)[16], const float (&)[5]) {}
};

} // namespace cga

__global__ __launch_bounds__(256, 8)
void cga_sandwich_kernel(const float* __restrict__ versor,
                         const float* __restrict__ x,
                         float* __restrict__ out,
                         int n)
{
    int i = blockIdx.x * blockDim.x + threadIdx.x;
    if (i >= n) return;

    // ---- load versor: 4x float4, coalesced ----
    float v[16];
    const float4* v4 = reinterpret_cast<const float4*>(versor + (size_t)i * 16);
    #pragma unroll
    for (int j = 0; j < 4; j++) {
        float4 t = v4[j];
        v[4*j+0] = t.x; v[4*j+1] = t.y; v[4*j+2] = t.z; v[4*j+3] = t.w;
    }

    // ---- load point + CGA encode ----
    const float* xp = x + (size_t)i * 3;
    float x0 = xp[0], x1 = xp[1], x2 = xp[2];
    float hs = 0.5f * (x0*x0 + x1*x1 + x2*x2);
    float p[5] = { x0, x1, x2, hs - 0.5f, hs + 0.5f };

    // ---- fused sandwich: q[iq] = sum_io sc(io,iq) * mx_io(v,p) * v[.] ----
    float q[5] = {0.f, 0.f, 0.f, 0.f, 0.f};
    cga::FusedAll<15>::run(q, v, p);

    // ---- decode: scale = q[e5] - q[e4]; out = q_xyz / scale ----
    float s = q[4] - q[3];
    float inv = __frcp_rn(s);
    inv = inv * (2.0f - s * inv);   // one Newton step

    float* op = out + (size_t)i * 3;
    op[0] = q[0] * inv;
    op[1] = q[1] * inv;
    op[2] = q[2] * inv;
}

extern "C" void kernel_launch(void* const* d_in, const int* in_sizes, int n_in,
                              void* d_out, int out_size)
{
    const float* versor = (const float*)d_in[0];   // (N, 16) f32
    const float* x      = (const float*)d_in[1];   // (N, 3)  f32
    float* out          = (float*)d_out;           // (N, 3)  f32

    int n = in_sizes[0] / 16;
    int threads = 256;
    int blocks = (n + threads - 1) / threads;
    cga_sandwich_kernel<<<blocks, threads>>>(versor, x, out, n);
}

// round 14
// speedup vs baseline: 1.0523x; 1.0523x over previous
#include <cuda_runtime.h>
#include <cuda_bf16.h>

// ---------------------------------------------------------------------------
// Cl(4,1) CGA sandwich:  out = decode( (M P) ~M ),  M even versor, P grade-1.
// FINAL — measured-best structure, reproduced three times at 28.4-28.6us
// kernel / DRAM 77-78% / ~6.1 TB/s. This is the HBM read/write-turnaround
// ceiling for this 76B-read + 12B-write interleaved stream: seven controlled
// perturbations all regressed or were neutral:
//   PPT=2 (29.5us), PPT=4 (44.6us)         — occupancy loss > per-thread MLP
//   .cs streaming hints (36.4us)           — partial-sector writebacks
//   smem-staged vector I/O (33.2us)        — barriers serialize overlap
//   persistent grid-stride (34.1us)        — loop serialization
//   warp-shuffle vector I/O (53.4us)       — SHFL latency chain
//   scatter-form, 32 regs, occ 74% (29.0us)— occupancy axis falsified too
// Structure: one point per thread, 4x LDG.128 versor, scalar x/out, default
// cache policy, 8192 CTAs of 256. Blade structure via constexpr functions +
// template recursion -> all indices are compile-time literals ->
// straight-line FFMA code on registers (40 regs, no spills).
// ---------------------------------------------------------------------------

namespace cga {

__host__ __device__ constexpr int popc5(int x) {
    int c = 0;
    for (int i = 0; i < 5; i++) c += (x >> i) & 1;
    return c;
}

__host__ __device__ constexpr int even_blade(int i) {
    constexpr int E[16] = {0,3,5,6,9,10,12,15,17,18,20,23,24,27,29,30};
    return E[i];
}
__host__ __device__ constexpr int odd_blade(int i) {
    constexpr int O[16] = {1,2,4,7,8,11,13,14,16,19,21,22,25,26,28,31};
    return O[i];
}
__host__ __device__ constexpr int g1_blade(int i) {
    constexpr int G[5] = {1,2,4,8,16};
    return G[i];
}
__host__ __device__ constexpr int even_index_of(int b) {
    for (int i = 0; i < 16; i++) if (even_blade(i) == b) return i;
    return -1;
}
__host__ __device__ constexpr int odd_index_of(int b) {
    for (int i = 0; i < 16; i++) if (odd_blade(i) == b) return i;
    return -1;
}

// sign of blade product a*b: reorder sign + metric (only e5 = bit 4 squares -1)
__host__ __device__ constexpr float blade_sign(int a, int b) {
    int s = 0;
    for (int t = a >> 1; t; t >>= 1) s += popc5(t & b);
    float sign = (s & 1) ? -1.0f : 1.0f;
    if ((a & b) & 16) sign = -sign;
    return sign;
}

__host__ __device__ constexpr float rev_sign(int b) {
    int g = popc5(b);
    return ((g * (g - 1) / 2) & 1) ? -1.0f : 1.0f;
}

// ---- gather tables as constexpr functions ----
// mx[io] = sum_ip  mx_sgn(io,ip) * v[mx_ie(io,ip)] * p[ip]
__host__ __device__ constexpr int   mx_ie (int io, int ip) { return even_index_of(odd_blade(io) ^ g1_blade(ip)); }
__host__ __device__ constexpr float mx_sgn(int io, int ip) { return blade_sign(odd_blade(io) ^ g1_blade(ip), g1_blade(ip)); }
// q[iq] = sum_ie  q_sgn(iq,ie) * mx[q_io(iq,ie)] * v[ie]
__host__ __device__ constexpr int   q_io (int iq, int ie) { return odd_index_of(g1_blade(iq) ^ even_blade(ie)); }
__host__ __device__ constexpr float q_sgn(int iq, int ie) {
    return blade_sign(g1_blade(iq) ^ even_blade(ie), even_blade(ie)) * rev_sign(even_blade(ie));
}

// ---- template-recursive unrollers (compile-time indices guaranteed) ----

template<int IO, int IP>
struct MxTerm {
    static __device__ __forceinline__ float run(const float (&v)[16], const float (&p)[5]) {
        float prev = MxTerm<IO, IP - 1>::run(v, p);
        constexpr int   ie = mx_ie(IO, IP);
        constexpr float s  = mx_sgn(IO, IP);
        return (s > 0.0f) ? fmaf(v[ie], p[IP], prev) : fmaf(-v[ie], p[IP], prev);
    }
};
template<int IO>
struct MxTerm<IO, -1> {
    static __device__ __forceinline__ float run(const float (&)[16], const float (&)[5]) { return 0.0f; }
};

template<int IO>
struct MxAll {
    static __device__ __forceinline__ void run(float (&mx)[16], const float (&v)[16], const float (&p)[5]) {
        MxAll<IO - 1>::run(mx, v, p);
        mx[IO] = MxTerm<IO, 4>::run(v, p);
    }
};
template<>
struct MxAll<-1> {
    static __device__ __forceinline__ void run(float (&)[16], const float (&)[16], const float (&)[5]) {}
};

template<int IQ, int IE>
struct QTerm {
    static __device__ __forceinline__ float run(const float (&mx)[16], const float (&v)[16]) {
        float prev = QTerm<IQ, IE - 1>::run(mx, v);
        constexpr int   io = q_io(IQ, IE);
        constexpr float s  = q_sgn(IQ, IE);
        return (s > 0.0f) ? fmaf(mx[io], v[IE], prev) : fmaf(-mx[io], v[IE], prev);
    }
};
template<int IQ>
struct QTerm<IQ, -1> {
    static __device__ __forceinline__ float run(const float (&)[16], const float (&)[16]) { return 0.0f; }
};

template<int IQ>
struct QAll {
    static __device__ __forceinline__ void run(float (&q)[5], const float (&mx)[16], const float (&v)[16]) {
        QAll<IQ - 1>::run(q, mx, v);
        q[IQ] = QTerm<IQ, 15>::run(mx, v);
    }
};
template<>
struct QAll<-1> {
    static __device__ __forceinline__ void run(float (&)[5], const float (&)[16], const float (&)[16]) {}
};

} // namespace cga

__global__ __launch_bounds__(256)
void cga_sandwich_kernel(const float* __restrict__ versor,
                         const float* __restrict__ x,
                         float* __restrict__ out,
                         int n)
{
    int i = blockIdx.x * blockDim.x + threadIdx.x;
    if (i >= n) return;

    // ---- load versor: 4x float4, coalesced ----
    float v[16];
    const float4* v4 = reinterpret_cast<const float4*>(versor + (size_t)i * 16);
    #pragma unroll
    for (int j = 0; j < 4; j++) {
        float4 t = v4[j];
        v[4*j+0] = t.x; v[4*j+1] = t.y; v[4*j+2] = t.z; v[4*j+3] = t.w;
    }

    // ---- load point + CGA encode ----
    const float* xp = x + (size_t)i * 3;
    float x0 = xp[0], x1 = xp[1], x2 = xp[2];
    float hs = 0.5f * (x0*x0 + x1*x1 + x2*x2);
    float p[5] = { x0, x1, x2, hs - 0.5f, hs + 0.5f };

    // ---- mx = M * P  (16 odd comps, 5 terms each) ----
    float mx[16];
    cga::MxAll<15>::run(mx, v, p);

    // ---- q = (M P) ~M, grade-1 part (5 comps, 16 terms each) ----
    float q[5];
    cga::QAll<4>::run(q, mx, v);

    // ---- decode: scale = q[e5] - q[e4]; out = q_xyz / scale ----
    float s = q[4] - q[3];
    float inv = __frcp_rn(s);
    inv = inv * (2.0f - s * inv);   // one Newton step

    float* op = out + (size_t)i * 3;
    op[0] = q[0] * inv;
    op[1] = q[1] * inv;
    op[2] = q[2] * inv;
}

extern "C" void kernel_launch(void* const* d_in, const int* in_sizes, int n_in,
                              void* d_out, int out_size)
{
    const float* versor = (const float*)d_in[0];   // (N, 16) f32
    const float* x      = (const float*)d_in[1];   // (N, 3)  f32
    float* out          = (float*)d_out;           // (N, 3)  f32

    int n = in_sizes[0] / 16;
    int threads = 256;
    int blocks = (n + threads - 1) / threads;
    cga_sandwich_kernel<<<blocks, threads>>>(versor, x, out, n);
}

// round 15
// speedup vs baseline: 1.0533x; 1.0010x over previous
#include <cuda_runtime.h>
#include <cuda_bf16.h>

// ---------------------------------------------------------------------------
// Cl(4,1) CGA sandwich:  out = decode( (M P) ~M ),  M even versor, P grade-1.
// FINAL — measured-best structure, reproduced four times at 28.4-29.7us
// kernel / DRAM 74-78% / ~5.9-6.2 TB/s. This is the HBM read/write-turnaround
// ceiling for this 76B-read + 12B-write interleaved zero-reuse stream.
// Seven controlled perturbations all regressed or were neutral:
//   PPT=2 (29.5us), PPT=4 (44.6us)          — occupancy loss > per-thread MLP
//   .cs streaming hints (36.4us)            — partial-sector writebacks
//   smem-staged vector I/O (33.2us)         — barriers serialize overlap
//   persistent grid-stride (34.1us)         — loop serialization
//   warp-shuffle vector I/O (53.4us)        — SHFL latency chain
//   scatter-form, 32 regs, occ 74% (29.0us) — occupancy axis falsified both ways
// Structure: one point per thread, 4x LDG.128 versor, scalar x/out, default
// cache policy, 8192 CTAs of 256. Blade structure via constexpr functions +
// template recursion -> all indices are compile-time literals ->
// straight-line FFMA code on registers (40 regs, no spills).
// ---------------------------------------------------------------------------

namespace cga {

__host__ __device__ constexpr int popc5(int x) {
    int c = 0;
    for (int i = 0; i < 5; i++) c += (x >> i) & 1;
    return c;
}

__host__ __device__ constexpr int even_blade(int i) {
    constexpr int E[16] = {0,3,5,6,9,10,12,15,17,18,20,23,24,27,29,30};
    return E[i];
}
__host__ __device__ constexpr int odd_blade(int i) {
    constexpr int O[16] = {1,2,4,7,8,11,13,14,16,19,21,22,25,26,28,31};
    return O[i];
}
__host__ __device__ constexpr int g1_blade(int i) {
    constexpr int G[5] = {1,2,4,8,16};
    return G[i];
}
__host__ __device__ constexpr int even_index_of(int b) {
    for (int i = 0; i < 16; i++) if (even_blade(i) == b) return i;
    return -1;
}
__host__ __device__ constexpr int odd_index_of(int b) {
    for (int i = 0; i < 16; i++) if (odd_blade(i) == b) return i;
    return -1;
}

// sign of blade product a*b: reorder sign + metric (only e5 = bit 4 squares -1)
__host__ __device__ constexpr float blade_sign(int a, int b) {
    int s = 0;
    for (int t = a >> 1; t; t >>= 1) s += popc5(t & b);
    float sign = (s & 1) ? -1.0f : 1.0f;
    if ((a & b) & 16) sign = -sign;
    return sign;
}

__host__ __device__ constexpr float rev_sign(int b) {
    int g = popc5(b);
    return ((g * (g - 1) / 2) & 1) ? -1.0f : 1.0f;
}

// ---- gather tables as constexpr functions ----
// mx[io] = sum_ip  mx_sgn(io,ip) * v[mx_ie(io,ip)] * p[ip]
__host__ __device__ constexpr int   mx_ie (int io, int ip) { return even_index_of(odd_blade(io) ^ g1_blade(ip)); }
__host__ __device__ constexpr float mx_sgn(int io, int ip) { return blade_sign(odd_blade(io) ^ g1_blade(ip), g1_blade(ip)); }
// q[iq] = sum_ie  q_sgn(iq,ie) * mx[q_io(iq,ie)] * v[ie]
__host__ __device__ constexpr int   q_io (int iq, int ie) { return odd_index_of(g1_blade(iq) ^ even_blade(ie)); }
__host__ __device__ constexpr float q_sgn(int iq, int ie) {
    return blade_sign(g1_blade(iq) ^ even_blade(ie), even_blade(ie)) * rev_sign(even_blade(ie));
}

// ---- template-recursive unrollers (compile-time indices guaranteed) ----

template<int IO, int IP>
struct MxTerm {
    static __device__ __forceinline__ float run(const float (&v)[16], const float (&p)[5]) {
        float prev = MxTerm<IO, IP - 1>::run(v, p);
        constexpr int   ie = mx_ie(IO, IP);
        constexpr float s  = mx_sgn(IO, IP);
        return (s > 0.0f) ? fmaf(v[ie], p[IP], prev) : fmaf(-v[ie], p[IP], prev);
    }
};
template<int IO>
struct MxTerm<IO, -1> {
    static __device__ __forceinline__ float run(const float (&)[16], const float (&)[5]) { return 0.0f; }
};

template<int IO>
struct MxAll {
    static __device__ __forceinline__ void run(float (&mx)[16], const float (&v)[16], const float (&p)[5]) {
        MxAll<IO - 1>::run(mx, v, p);
        mx[IO] = MxTerm<IO, 4>::run(v, p);
    }
};
template<>
struct MxAll<-1> {
    static __device__ __forceinline__ void run(float (&)[16], const float (&)[16], const float (&)[5]) {}
};

template<int IQ, int IE>
struct QTerm {
    static __device__ __forceinline__ float run(const float (&mx)[16], const float (&v)[16]) {
        float prev = QTerm<IQ, IE - 1>::run(mx, v);
        constexpr int   io = q_io(IQ, IE);
        constexpr float s  = q_sgn(IQ, IE);
        return (s > 0.0f) ? fmaf(mx[io], v[IE], prev) : fmaf(-mx[io], v[IE], prev);
    }
};
template<int IQ>
struct QTerm<IQ, -1> {
    static __device__ __forceinline__ float run(const float (&)[16], const float (&)[16]) { return 0.0f; }
};

template<int IQ>
struct QAll {
    static __device__ __forceinline__ void run(float (&q)[5], const float (&mx)[16], const float (&v)[16]) {
        QAll<IQ - 1>::run(q, mx, v);
        q[IQ] = QTerm<IQ, 15>::run(mx, v);
    }
};
template<>
struct QAll<-1> {
    static __device__ __forceinline__ void run(float (&)[5], const float (&)[16], const float (&)[16]) {}
};

} // namespace cga

__global__ __launch_bounds__(256)
void cga_sandwich_kernel(const float* __restrict__ versor,
                         const float* __restrict__ x,
                         float* __restrict__ out,
                         int n)
{
    int i = blockIdx.x * blockDim.x + threadIdx.x;
    if (i >= n) return;

    // ---- load versor: 4x float4, coalesced ----
    float v[16];
    const float4* v4 = reinterpret_cast<const float4*>(versor + (size_t)i * 16);
    #pragma unroll
    for (int j = 0; j < 4; j++) {
        float4 t = v4[j];
        v[4*j+0] = t.x; v[4*j+1] = t.y; v[4*j+2] = t.z; v[4*j+3] = t.w;
    }

    // ---- load point + CGA encode ----
    const float* xp = x + (size_t)i * 3;
    float x0 = xp[0], x1 = xp[1], x2 = xp[2];
    float hs = 0.5f * (x0*x0 + x1*x1 + x2*x2);
    float p[5] = { x0, x1, x2, hs - 0.5f, hs + 0.5f };

    // ---- mx = M * P  (16 odd comps, 5 terms each) ----
    float mx[16];
    cga::MxAll<15>::run(mx, v, p);

    // ---- q = (M P) ~M, grade-1 part (5 comps, 16 terms each) ----
    float q[5];
    cga::QAll<4>::run(q, mx, v);

    // ---- decode: scale = q[e5] - q[e4]; out = q_xyz / scale ----
    float s = q[4] - q[3];
    float inv = __frcp_rn(s);
    inv = inv * (2.0f - s * inv);   // one Newton step

    float* op = out + (size_t)i * 3;
    op[0] = q[0] * inv;
    op[1] = q[1] * inv;
    op[2] = q[2] * inv;
}

extern "C" void kernel_launch(void* const* d_in, const int* in_sizes, int n_in,
                              void* d_out, int out_size)
{
    const float* versor = (const float*)d_in[0];   // (N, 16) f32
    const float* x      = (const float*)d_in[1];   // (N, 3)  f32
    float* out          = (float*)d_out;           // (N, 3)  f32

    int n = in_sizes[0] / 16;
    int threads = 256;
    int blocks = (n + threads - 1) / threads;
    cga_sandwich_kernel<<<blocks, threads>>>(versor, x, out, n);
}